// round 8
// baseline (speedup 1.0000x reference)
#include <cuda_runtime.h>
#include <cstdint>
#include <cstddef>

#define BATCH 8
#define CH 64
#define HH 256
#define WW 256
#define MM 12
#define KXM 24
#define NLAYERS 4
#define FCH 128
#define HW (HH*WW)
#define BCHW (BATCH*CH*HW)
#define PADH 260

// ---------------- device scratch ----------------
__device__ float g_h[BCHW];                    // activations [b,c,x,y] (boundaries 0..2)
__device__ float g_Fy[BATCH*MM*CH*HH*2];       // [b][ky][c][x] float2
__device__ float g_E [BATCH*HH*CH*KXM];        // [b][x][o][ke]
// pre-fragmented constant operands (tf32)
__device__ float g_TYF[3*16*32*4];             // A-frags TYinv (k_layer kk 8..10)
__device__ float g_PWF[NLAYERS*8*8*32*2];      // B-frags pw weights per layer
__device__ float g_FC1F[8*16*32*2];            // B-frags fc1 weights
__device__ float g_TYBF[32*3*32*2];            // B-frags forward y-DFT basis
__device__ float g_F1A[64*3*32*4];             // A-frags fwd x-DFT (M=48,K=512)
__device__ float g_F2B[6*64*32*2];             // B-frags inv x-DFT (K=48,N=512), /65536
__device__ float g_WMIX[NLAYERS*MM*KXM*CH*CH*2]; // [l][ky][j][i][o] float2

// Fast GELU: Abramowitz-Stegun 7.1.26 erf approximation, |abs err| <= 1.5e-7
__device__ __forceinline__ float gelu_f(float v){
    float z = fabsf(v)*0.70710678118654752f;
    float t = __fdividef(1.0f, fmaf(0.3275911f, z, 1.0f));
    float p = fmaf(1.061405429f, t, -1.453152027f);
    p = fmaf(p, t, 1.421413741f);
    p = fmaf(p, t, -0.284496736f);
    p = fmaf(p, t, 0.254829592f);
    p *= t;
    float e = __expf(-z*z);
    float er = fmaf(-p, e, 1.0f);
    return v * (0.5f*(1.0f + copysignf(er, v)));
}
__device__ __forceinline__ float f2tf32(float x){
    uint32_t r; asm("cvt.rna.tf32.f32 %0, %1;" : "=r"(r) : "f"(x));
    return __uint_as_float(r);
}
__device__ __forceinline__ void mma_tf32(float& d0,float& d1,float& d2,float& d3,
                                         float a0,float a1,float a2,float a3,
                                         float b0,float b1){
    asm volatile("mma.sync.aligned.m16n8k8.row.col.f32.tf32.tf32.f32 "
        "{%0,%1,%2,%3}, {%4,%5,%6,%7}, {%8,%9}, {%0,%1,%2,%3};"
        : "+f"(d0),"+f"(d1),"+f"(d2),"+f"(d3)
        : "r"(__float_as_uint(a0)),"r"(__float_as_uint(a1)),
          "r"(__float_as_uint(a2)),"r"(__float_as_uint(a3)),
          "r"(__float_as_uint(b0)),"r"(__float_as_uint(b1)));
}

// ---------------- fused y-DFT epilogue (4-warp, R6 form) ----------------
__device__ __forceinline__ void dft_epi(const float* __restrict__ HS, int b, int xr,
                                        int warp, int lane){
    if (warp >= 4) return;
    int g = lane>>2, t4 = lane&3;
    int mt = warp;
    float c[3][4];
#pragma unroll
    for (int nt=0;nt<3;nt++)
#pragma unroll
        for (int r=0;r<4;r++) c[nt][r]=0.f;
    const float2* TB = (const float2*)g_TYBF;
    for (int kk=0; kk<32; kk++){
        float a0 = HS[(mt*16+g  )*PADH + kk*8+t4];
        float a1 = HS[(mt*16+g+8)*PADH + kk*8+t4];
        float a2 = HS[(mt*16+g  )*PADH + kk*8+t4+4];
        float a3 = HS[(mt*16+g+8)*PADH + kk*8+t4+4];
#pragma unroll
        for (int nt=0;nt<3;nt++){
            float2 bf = __ldg(TB + (kk*3+nt)*32 + lane);
            mma_tf32(c[nt][0],c[nt][1],c[nt][2],c[nt][3], a0,a1,a2,a3, bf.x,bf.y);
        }
    }
    float2* Fy2 = (float2*)g_Fy;
    int o = mt*16+g;
#pragma unroll
    for (int nt=0;nt<3;nt++){
        int ky = nt*4+t4;
        size_t base = (((size_t)(b*MM+ky)*CH + o)<<8) + xr;
        Fy2[base]          = make_float2(c[nt][0], c[nt][1]);
        Fy2[base + (8<<8)] = make_float2(c[nt][2], c[nt][3]);
    }
}

// ---------------- fragment pre-pack ----------------
__global__ void k_frw(const float* __restrict__ pw_w, const float* __restrict__ fc1w){
    int t = blockIdx.x*blockDim.x + threadIdx.x;
    if (t < 6144){                                  // TYinv A-frags
        int k = t>>8, y = t&255;
        int ky2 = k>>1;
        int r2 = (ky2*y) & 255;
        double s2,c2; sincospi(2.0*r2/256.0, &s2, &c2);
        float v;
        if ((k&1)==0) v = (ky2==0)? 1.0f : 2.0f*(float)c2;
        else          v = (ky2==0)? 0.0f : -2.0f*(float)s2;
        int kk=k>>3, kin=k&7, t4=kin&3, kh=kin>>2;
        int yt=y>>4, yin=y&15, g=yin&7, half=yin>>3;
        g_TYF[(((kk*16+yt)<<5) + ((g<<2)|t4))*4 + ((kh<<1)|half)] = f2tf32(v);
    } else if (t < 22528){                          // pw B-frags
        int u = t - 6144;
        int layer = u>>12; int v = u&4095;
        int k = v&63, o = v>>6;
        float w = pw_w[(layer*CH+o)*CH + k];
        int kk=k>>3, kin=k&7, t4=kin&3, kh=kin>>2;
        int ot=o>>3, g=o&7;
        g_PWF[layer*4096 + (((kk*8+ot)<<5)+((g<<2)|t4))*2 + kh] = f2tf32(w);
    } else if (t < 30720){                          // fc1 B-frags
        int u = t - 22528;
        int i = u&63, f = u>>6;
        float w = fc1w[f*CH + i];
        int kk=i>>3, kin=i&7, t4=kin&3, kh=kin>>2;
        int ot=f>>3, g=f&7;
        g_FC1F[(((kk*16+ot)<<5)+((g<<2)|t4))*2 + kh] = f2tf32(w);
    } else if (t < 36864){                          // forward-DFT (y) B-frags
        int u = t - 30720;
        int kk = u/192; int r = u%192;
        int nt = r/64;  int r2 = r%64;
        int lane = r2>>1, kh = r2&1;
        int t4 = lane&3, g = lane>>2;
        int y = kk*8 + t4 + 4*kh;
        int n = nt*8 + g;
        int k = n>>1;
        int rr = (k*y) & 255;
        double s,c; sincospi(2.0*rr/256.0, &s, &c);
        float v = (n&1)? (float)(-s) : (float)c;
        g_TYBF[((kk*3+nt)*32 + lane)*2 + kh] = f2tf32(v);
    } else if (t < 61440){                          // fwd x-DFT A-frags
        int u = t - 36864;
        int slot = u&3, lane = (u>>2)&31, mt = (u>>7)%3, kk = u/384;
        int g = lane>>2, t4 = lane&3, half = slot&1, kh = slot>>1;
        int m = mt*16 + g + 8*half;
        int k = kk*8 + t4 + 4*kh;
        int j = m>>1, ri = m&1;
        int x = k>>1, xi = k&1;
        int keff = (j<12)? j : (j-24);
        int rr = ((keff*x)%256 + 256) & 255;
        double s,c; sincospi(2.0*rr/256.0, &s, &c);
        float v = (ri==0) ? ((xi==0)? (float)c : (float)s)
                          : ((xi==0)? (float)(-s) : (float)c);
        g_F1A[u] = f2tf32(v);
    } else if (t < 86016){                          // inv x-DFT B-frags
        int u = t - 61440;
        int kh = u&1, lane = (u>>1)&31, nt = (u>>6)&63, kk = u>>12;
        int g = lane>>2, t4 = lane&3;
        int k = kk*8 + t4 + 4*kh;
        int j = k>>1, ri = k&1;
        int n = nt*8 + g;
        int x = n>>1, xi = n&1;
        int keff = (j<12)? j : (j-24);
        int rr = ((keff*x)%256 + 256) & 255;
        double s,c; sincospi(2.0*rr/256.0, &s, &c);
        float v = (ri==0) ? ((xi==0)? (float)c : (float)s)
                          : ((xi==0)? (float)(-s) : (float)c);
        g_F2B[u] = f2tf32(v * (1.0f/65536.0f));
    }
}

// ---------------- weight transpose via smem (coalesced both sides) ----------------
#define WMIX_SMEM (2*64*145*4)
__global__ void __launch_bounds__(256) k_wmix(const float* __restrict__ w1,
                                              const float* __restrict__ w2){
    extern __shared__ float sm[];
    float* sre = sm;
    float* sim = sm + 64*145;
    int blk = blockIdx.x;            // 512 = 4l * 64i * 2(which)
    int which = blk & 1;
    int li = blk >> 1;
    const float2* src = ((const float2*)(which? w2 : w1)) + (size_t)li*9216;
    for (int t=threadIdx.x; t<9216; t+=256){
        float2 v = src[t];
        int o = t/144, jk = t - o*144;
        sre[o*145+jk] = v.x;
        sim[o*145+jk] = v.y;
    }
    __syncthreads();
    int l = li>>6, i = li&63;
    int warp = threadIdx.x>>5, lane = threadIdx.x&31;
    for (int jk=warp; jk<144; jk+=8){
        int jm = jk/12, ky = jk - jm*12;
        int j = jm + (which? 12:0);
        float2* dst = ((float2*)g_WMIX) + ((size_t)((l*12+ky)*24 + j))*4096 + i*64;
        dst[lane]    = make_float2(sre[lane*145+jk],      sim[lane*145+jk]);
        dst[lane+32] = make_float2(sre[(lane+32)*145+jk], sim[(lane+32)*145+jk]);
    }
}

// ---------------- lift (fc0) -> Fy only, parallel fc0 + 4-warp epi ----------------
#define LIFT_SMEM ((CH*PADH + 256)*4)
__global__ void __launch_bounds__(256) k_lift_fy(const float* __restrict__ x,
                                                 const float* __restrict__ fw,
                                                 const float* __restrict__ fb){
    extern __shared__ float HS[];   // [64][PADH]
    float* xs = HS + CH*PADH;       // 256
    int b = blockIdx.x>>8, xr = blockIdx.x&255;
    int tid = threadIdx.x;
    if (tid < 64)
        ((float4*)xs)[tid] = ((const float4*)(x + (((size_t)b)<<16) + (xr<<8)))[tid];
    __syncthreads();
    float gx = xr*(1.0f/255.0f);
    for (int t=tid; t<CH*64; t+=256){
        int i=t>>6, q=t&63;
        float w0=__ldg(fw+i*3), w1=__ldg(fw+i*3+1), w2=__ldg(fw+i*3+2);
        float base = w1*gx + __ldg(fb+i);
        float4 hv;
        hv.x = f2tf32(w0*xs[q*4  ] + w2*((q*4  )*(1.0f/255.0f)) + base);
        hv.y = f2tf32(w0*xs[q*4+1] + w2*((q*4+1)*(1.0f/255.0f)) + base);
        hv.z = f2tf32(w0*xs[q*4+2] + w2*((q*4+2)*(1.0f/255.0f)) + base);
        hv.w = f2tf32(w0*xs[q*4+3] + w2*((q*4+3)*(1.0f/255.0f)) + base);
        ((float4*)(HS + i*PADH))[q] = hv;
    }
    __syncthreads();
    dft_epi(HS, b, xr, tid>>5, tid&31);
}

// ---------------- K-spec: fused (x-DFT -> mode mix -> x-inverse) per (b,ky) ----------------
#define BF1_F2 (64*8*32)
#define G_STRIDE 65
#define G_F (48*G_STRIDE)
#define AF2_F (6*4*32*4)
#define PB1_F (48*128)
#define SPEC_SMEM ((BF1_F2*2 + G_F + AF2_F + PB1_F)*4)

__global__ void __launch_bounds__(512,1)
k_spec(int layer){
    extern __shared__ float sm[];
    float* BF1f = sm;
    float* Gs   = sm + 2*BF1_F2;
    float* AF2  = Gs + G_F;
    float* PB   = AF2 + AF2_F;           // [48 units][32 lanes][4]
    int b = blockIdx.x/12, ky = blockIdx.x%12;
    int tid = threadIdx.x, lane = tid&31, warp = tid>>5;

    const float2* fy = ((const float2*)g_Fy) + (((size_t)(b*MM+ky))<<14);
    for (int t=tid; t<64*256; t+=512){
        int c = t>>8, x = t&255;
        float2 v = fy[t];
        int nt=c>>3, g=c&7;
        int k0=2*x;
        int kk=k0>>3, t4=k0&3, kh=(k0>>2)&1;
        int base = ((kk*8+nt)<<5);
        BF1f[(base + ((g<<2)|t4    ))*2 + kh] = f2tf32(v.x);
        BF1f[(base + ((g<<2)|(t4+1)))*2 + kh] = f2tf32(v.y);
    }
    __syncthreads();

    // GEMM1 balanced split-k: 48 units = 24 tiles x 2 K-halves, 3 per warp
    {
        const float4* A4 = (const float4*)g_F1A;
        const float2* B2 = (const float2*)BF1f;
        for (int u=warp; u<48; u+=16){
            int tile = u%24, khalf = u/24;
            int mt = tile%3, nt = tile/3;
            float c0=0.f,c1=0.f,c2=0.f,c3=0.f;
            int kb = khalf*32;
#pragma unroll 8
            for (int kk=kb; kk<kb+32; kk++){
                float4 a = __ldg(A4 + ((kk*3+mt)<<5)+lane);
                float2 bf = B2[((kk*8+nt)<<5)+lane];
                mma_tf32(c0,c1,c2,c3, a.x,a.y,a.z,a.w, bf.x,bf.y);
            }
            float* pb = PB + u*128 + lane*4;
            pb[0]=c0; pb[1]=c1; pb[2]=c2; pb[3]=c3;
        }
    }
    __syncthreads();
    // reduce 2 halves into Gs[48][65]
    for (int t=tid; t<3072; t+=512){
        int row = t>>6, col = t&63;
        int mt = row>>4, rr = row&15, g = rr&7, hi = rr>>3;
        int nt = col>>3, cc = col&7, t4 = cc>>1, r0 = (hi<<1)|(cc&1);
        int lidx = g*4+t4;
        int tile = nt*3+mt;
        Gs[row*G_STRIDE+col] = PB[tile*128 + lidx*4 + r0]
                             + PB[(tile+24)*128 + lidx*4 + r0];
    }
    __syncthreads();

    // mix: G2[o][j] = sum_i G[i][j] * W[i][o], dual accumulators
    {
        const float2* WM = ((const float2*)g_WMIX) + ((size_t)((layer*12+ky)*24))*4096;
#pragma unroll
        for (int r=0; r<3; r++){
            int item = tid + 512*r;
            int j = item>>6, o = item&63;
            const float2* wrow = WM + j*4096 + o;
            const float* Gr = Gs + (2*j)*G_STRIDE;
            const float* Gi = Gs + (2*j+1)*G_STRIDE;
            float ar0=0.f, ai0=0.f, ar1=0.f, ai1=0.f;
#pragma unroll 8
            for (int i=0;i<64;i+=2){
                float2 wv0 = __ldg(wrow + i*64);
                float2 wv1 = __ldg(wrow + (i+1)*64);
                float g0r = Gr[i],   g0i = Gi[i];
                float g1r = Gr[i+1], g1i = Gi[i+1];
                ar0 += g0r*wv0.x - g0i*wv0.y;
                ai0 += g0r*wv0.y + g0i*wv0.x;
                ar1 += g1r*wv1.x - g1i*wv1.y;
                ai1 += g1r*wv1.y + g1i*wv1.x;
            }
            float ar = ar0+ar1, ai = ai0+ai1;
            int mt=o>>4, half=(o>>3)&1, gg=o&7;
            int k0=2*j;
            int kk=k0>>3, t40=k0&3, kh=(k0>>2)&1;
            int base = ((kk*4+mt)<<5);
            AF2[(base + ((gg<<2)|t40    ))*4 + ((kh<<1)|half)] = f2tf32(ar);
            AF2[(base + ((gg<<2)|(t40+1)))*4 + ((kh<<1)|half)] = f2tf32(ai);
        }
    }
    __syncthreads();

    // GEMM2: E[o][n=2x+ri] = AF2 x B(inv twiddle)
    {
        int mt = warp&3, ntb = (warp>>2)<<4;
        float4 Areg[6];
#pragma unroll
        for (int kk=0;kk<6;kk++)
            Areg[kk] = ((const float4*)AF2)[((kk*4+mt)<<5)+lane];
        int g=lane>>2, t4=lane&3;
        const float2* B2 = (const float2*)g_F2B;
        float2* E2 = (float2*)g_E;
        for (int ni=0;ni<16;ni++){
            int nt = ntb+ni;
            float c0=0.f,c1=0.f,c2=0.f,c3=0.f;
#pragma unroll
            for (int kk=0;kk<6;kk++){
                float2 bf = __ldg(B2 + ((kk*64+nt)<<5)+lane);
                mma_tf32(c0,c1,c2,c3, Areg[kk].x,Areg[kk].y,Areg[kk].z,Areg[kk].w,
                         bf.x,bf.y);
            }
            int x = nt*4+t4, o = mt*16+g;
            E2[((size_t)(b*HH+x)*CH + o  )*12 + ky] = make_float2(c0,c1);
            E2[((size_t)(b*HH+x)*CH + o+8)*12 + ky] = make_float2(c2,c3);
        }
    }
}

// ---------------- K5: fused layer; layer0 recomputes lift; layer3 fuses head ------------
#define K5_SMEM ((16640 + 1536 + 64 + 256)*4)

__global__ void __launch_bounds__(256,2)
k_layer(const float* __restrict__ xg, const float* __restrict__ fc0w,
        const float* __restrict__ fc0b, const float* __restrict__ pw_b,
        const float* __restrict__ fc1b, const float* __restrict__ fc2w,
        const float* __restrict__ fc2b, float* __restrict__ out, int layer){
    extern __shared__ float sm[];
    float* AF = sm;                  // h A-frags (16384) / HS overlay (16640) / head-AF
    float* HS = sm;
    float* EF = sm + 16640;          // E B-frags (1536) / head partials
    float* bs = EF + 1536;
    float* xs = bs + 64;
    int b = blockIdx.x >> 8, xr = blockIdx.x & 255;
    int tid = threadIdx.x;

    if (layer == 0){
        if (tid < 64)
            ((float4*)xs)[tid] = ((const float4*)(xg + (((size_t)b)<<16) + (xr<<8)))[tid];
        __syncthreads();
        float gx = xr*(1.0f/255.0f);
        for (int t=tid; t<CH*64; t+=256){
            int i=t>>6, q=t&63;
            float w0=__ldg(fc0w+i*3), w1=__ldg(fc0w+i*3+1), w2=__ldg(fc0w+i*3+2);
            float base = w1*gx + __ldg(fc0b+i);
            int kk=i>>3, kin=i&7, t4=kin&3, kh=kin>>2;
#pragma unroll
            for (int d=0; d<4; d++){
                int y = q*4+d;
                float v = w0*xs[y] + w2*(y*(1.0f/255.0f)) + base;
                int yt=y>>4, yin=y&15, g=yin&7, half=yin>>3;
                AF[(((kk*16+yt)<<5)+((g<<2)|t4))*4 + ((kh<<1)|half)] = f2tf32(v);
            }
        }
    } else {
        for (int t=tid; t<CH*64; t+=256){
            int i=t>>6, q=t&63;
            float4 v = ((const float4*)(g_h + (((size_t)(b*CH+i))<<16) + (xr<<8)))[q];
            int kk=i>>3, kin=i&7, t4=kin&3, kh=kin>>2;
            float vv[4] = {v.x, v.y, v.z, v.w};
#pragma unroll
            for (int d=0; d<4; d++){
                int y = q*4+d; int yt=y>>4, yin=y&15, g=yin&7, half=yin>>3;
                AF[(((kk*16+yt)<<5)+((g<<2)|t4))*4 + ((kh<<1)|half)] = f2tf32(vv[d]);
            }
        }
    }
    {   // E (coalesced) -> B-frags
        const float* Eb = g_E + ((size_t)(b*HH+xr))*CH*24;
        for (int t=tid; t<KXM*CH; t+=256){
            float v = Eb[t];
            int o = t/24, ke = t%24;
            int kk=ke>>3, t4=ke&3, kh=(ke>>2)&1;
            int ot=o>>3, g=o&7;
            EF[(((kk*8+ot)<<5)+((g<<2)|t4))*2 + kh] = f2tf32(v);
        }
    }
    if (tid<CH) bs[tid]=pw_b[layer*CH+tid];
    __syncthreads();

    int lane = tid & 31, warp = tid >> 5;
    int wy = warp >> 1, wo = warp & 1;

    float c[4][4][4];
#pragma unroll
    for (int mi=0;mi<4;mi++)
#pragma unroll
        for (int ni=0;ni<4;ni++)
#pragma unroll
            for (int r=0;r<4;r++) c[mi][ni][r]=0.f;

    const float2* PW2 = ((const float2*)g_PWF) + layer*2048;
    for (int kk=0; kk<8; kk++){
        float2 bf[4];
#pragma unroll
        for (int ni=0;ni<4;ni++)
            bf[ni] = __ldg(PW2 + ((kk*8 + wo*4+ni)<<5)+lane);
#pragma unroll
        for (int mi=0;mi<4;mi++){
            float4 af = ((const float4*)AF)[((kk*16 + wy*4+mi)<<5)+lane];
#pragma unroll
            for (int ni=0;ni<4;ni++)
                mma_tf32(c[mi][ni][0],c[mi][ni][1],c[mi][ni][2],c[mi][ni][3],
                         af.x,af.y,af.z,af.w, bf[ni].x, bf[ni].y);
        }
    }
    const float4* TY4 = (const float4*)g_TYF;
    for (int kk=0; kk<3; kk++){
        float2 bf[4];
#pragma unroll
        for (int ni=0;ni<4;ni++)
            bf[ni] = ((const float2*)EF)[((kk*8 + wo*4+ni)<<5)+lane];
#pragma unroll
        for (int mi=0;mi<4;mi++){
            float4 af = __ldg(TY4 + ((kk*16 + wy*4+mi)<<5)+lane);
#pragma unroll
            for (int ni=0;ni<4;ni++)
                mma_tf32(c[mi][ni][0],c[mi][ni][1],c[mi][ni][2],c[mi][ni][3],
                         af.x,af.y,af.z,af.w, bf[ni].x, bf[ni].y);
        }
    }

    int g = lane>>2, t4 = lane&3;
    int dogelu = (layer < NLAYERS-1);
#pragma unroll
    for (int mi=0;mi<4;mi++){
#pragma unroll
        for (int ni=0;ni<4;ni++){
            int o = (wo*4+ni)*8 + 2*t4;
            float bb0 = bs[o], bb1 = bs[o+1];
            float v0 = c[mi][ni][0] + bb0;
            float v1 = c[mi][ni][1] + bb1;
            float v2 = c[mi][ni][2] + bb0;
            float v3 = c[mi][ni][3] + bb1;
            if (dogelu){ v0=gelu_f(v0); v1=gelu_f(v1); v2=gelu_f(v2); v3=gelu_f(v3); }
            c[mi][ni][0]=v0; c[mi][ni][1]=v1; c[mi][ni][2]=v2; c[mi][ni][3]=v3;
        }
    }

    if (layer < NLAYERS-1){
#pragma unroll
        for (int mi=0;mi<4;mi++){
            int y = (wy*4+mi)*16 + g;
#pragma unroll
            for (int ni=0;ni<4;ni++){
                int o = (wo*4+ni)*8 + 2*t4;
                float* p0 = g_h + (((size_t)(b*CH+o  ))<<16) + (xr<<8);
                float* p1 = g_h + (((size_t)(b*CH+o+1))<<16) + (xr<<8);
                p0[y]   = c[mi][ni][0];
                p1[y]   = c[mi][ni][1];
                p0[y+8] = c[mi][ni][2];
                p1[y+8] = c[mi][ni][3];
            }
        }
        __syncthreads();
#pragma unroll
        for (int mi=0;mi<4;mi++){
            int y = (wy*4+mi)*16 + g;
#pragma unroll
            for (int ni=0;ni<4;ni++){
                int o = (wo*4+ni)*8 + 2*t4;
                HS[ o   *PADH + y  ] = f2tf32(c[mi][ni][0]);
                HS[(o+1)*PADH + y  ] = f2tf32(c[mi][ni][1]);
                HS[ o   *PADH + y+8] = f2tf32(c[mi][ni][2]);
                HS[(o+1)*PADH + y+8] = f2tf32(c[mi][ni][3]);
            }
        }
        __syncthreads();
        dft_epi(HS, b, xr, warp, lane);
        return;
    }

    // ---------------- layer 3: fused head ----------------
    __syncthreads();
#pragma unroll
    for (int mi=0;mi<4;mi++){
#pragma unroll
        for (int ni=0;ni<4;ni++){
#pragma unroll
            for (int r=0;r<4;r++){
                int o = (wo*4+ni)*8 + 2*t4 + (r&1);
                int y = (wy*4+mi)*16 + g + ((r>>1)<<3);
                int kk=o>>3, kin=o&7, t4n=kin&3, khn=kin>>2;
                int yt=y>>4, yin=y&15, gn=yin&7, halfn=yin>>3;
                AF[(((kk*16+yt)<<5)+((gn<<2)|t4n))*4 + ((khn<<1)|halfn)] =
                    f2tf32(c[mi][ni][r]);
            }
        }
    }
    __syncthreads();

    float* part = EF;
    float s0[4] = {0.f,0.f,0.f,0.f}, s1[4] = {0.f,0.f,0.f,0.f};
    const float2* F2 = (const float2*)g_FC1F;
#pragma unroll
    for (int p=0; p<2; p++){
#pragma unroll
        for (int mi=0;mi<4;mi++)
#pragma unroll
            for (int ni=0;ni<4;ni++)
#pragma unroll
                for (int r=0;r<4;r++) c[mi][ni][r]=0.f;
        for (int kk=0; kk<8; kk++){
            float2 bf[4];
#pragma unroll
            for (int ni=0;ni<4;ni++)
                bf[ni] = __ldg(F2 + ((kk*16 + p*8 + wo*4+ni)<<5)+lane);
#pragma unroll
            for (int mi=0;mi<4;mi++){
                float4 af = ((const float4*)AF)[((kk*16 + wy*4+mi)<<5)+lane];
#pragma unroll
                for (int ni=0;ni<4;ni++)
                    mma_tf32(c[mi][ni][0],c[mi][ni][1],c[mi][ni][2],c[mi][ni][3],
                             af.x,af.y,af.z,af.w, bf[ni].x, bf[ni].y);
            }
        }
#pragma unroll
        for (int mi=0;mi<4;mi++){
#pragma unroll
            for (int ni=0;ni<4;ni++){
                int f = (p*8 + wo*4+ni)*8 + 2*t4;
                float ba = __ldg(fc1b+f), bb = __ldg(fc1b+f+1);
                float wa = __ldg(fc2w+f), wb = __ldg(fc2w+f+1);
                s0[mi] += gelu_f(c[mi][ni][0]+ba)*wa + gelu_f(c[mi][ni][1]+bb)*wb;
                s1[mi] += gelu_f(c[mi][ni][2]+ba)*wa + gelu_f(c[mi][ni][3]+bb)*wb;
            }
        }
    }
#pragma unroll
    for (int mi=0;mi<4;mi++){
        float a0 = s0[mi], a1 = s1[mi];
        a0 += __shfl_xor_sync(0xffffffffu, a0, 1);
        a0 += __shfl_xor_sync(0xffffffffu, a0, 2);
        a1 += __shfl_xor_sync(0xffffffffu, a1, 1);
        a1 += __shfl_xor_sync(0xffffffffu, a1, 2);
        if (t4==0){
            int y = (wy*4+mi)*16 + g;
            part[wo*WW + y]   = a0;
            part[wo*WW + y+8] = a1;
        }
    }
    __syncthreads();
    {
        int y = tid;
        float s = part[y] + part[WW+y] + __ldg(fc2b);
        out[(((size_t)b)<<16) + (xr<<8) + y] = s;
    }
}

// ---------------- launch ----------------
extern "C" void kernel_launch(void* const* d_in, const int* in_sizes, int n_in,
                              void* d_out, int out_size){
    (void)in_sizes; (void)n_in; (void)out_size;
    const float* x     = (const float*)d_in[0];
    const float* fc0_w = (const float*)d_in[1];
    const float* fc0_b = (const float*)d_in[2];
    const float* w1    = (const float*)d_in[3];
    const float* w2    = (const float*)d_in[4];
    const float* pw_w  = (const float*)d_in[5];
    const float* pw_b  = (const float*)d_in[6];
    const float* fc1_w = (const float*)d_in[7];
    const float* fc1_b = (const float*)d_in[8];
    const float* fc2_w = (const float*)d_in[9];
    const float* fc2_b = (const float*)d_in[10];
    float* out = (float*)d_out;

    cudaFuncSetAttribute(k_layer,   cudaFuncAttributeMaxDynamicSharedMemorySize, K5_SMEM);
    cudaFuncSetAttribute(k_spec,    cudaFuncAttributeMaxDynamicSharedMemorySize, SPEC_SMEM);
    cudaFuncSetAttribute(k_lift_fy, cudaFuncAttributeMaxDynamicSharedMemorySize, LIFT_SMEM);
    cudaFuncSetAttribute(k_wmix,    cudaFuncAttributeMaxDynamicSharedMemorySize, WMIX_SMEM);

    k_frw<<<336,256>>>(pw_w, fc1_w);
    k_wmix<<<512,256,WMIX_SMEM>>>(w1, w2);
    k_lift_fy<<<BATCH*HH,256,LIFT_SMEM>>>(x, fc0_w, fc0_b);
    for (int l=0; l<NLAYERS; l++){
        k_spec<<<BATCH*MM,512,SPEC_SMEM>>>(l);
        k_layer<<<BATCH*HH,256,K5_SMEM>>>(x, fc0_w, fc0_b, pw_b,
                                          fc1_b, fc2_w, fc2_b, out, l);
    }
}

// round 9
// speedup vs baseline: 1.0612x; 1.0612x over previous
#include <cuda_runtime.h>
#include <cstdint>
#include <cstddef>

#define BATCH 8
#define CH 64
#define HH 256
#define WW 256
#define MM 12
#define KXM 24
#define NLAYERS 4
#define FCH 128
#define HW (HH*WW)
#define BCHW (BATCH*CH*HW)
#define PADH 260

// ---------------- device scratch ----------------
// g_h now stores the tf32-rounded MMA A-fragment image per (b,xr) row:
// 16384 floats at base blockIdx*16384.
__device__ float g_h[BCHW];
__device__ float g_Fy[BATCH*MM*CH*HH*2];       // [b][ky][c][x] float2
__device__ float g_E [BATCH*HH*CH*KXM];        // [b][x][o][ke]
// pre-fragmented constant operands (tf32)
__device__ float g_TYF[3*16*32*4];             // A-frags TYinv (k_layer kk 8..10)
__device__ float g_PWF[NLAYERS*8*8*32*2];      // B-frags pw weights per layer
__device__ float g_FC1F[8*16*32*2];            // B-frags fc1 weights
__device__ float g_TYBF[32*3*32*2];            // B-frags forward y-DFT basis
__device__ float g_F1A[64*3*32*4];             // A-frags fwd x-DFT (M=48,K=512)
__device__ float g_F2B[6*64*32*2];             // B-frags inv x-DFT (K=48,N=512), /65536
__device__ float g_WMIX[NLAYERS*MM*KXM*CH*CH*2]; // [l][ky][j][i][o] float2

// Fast GELU: Abramowitz-Stegun 7.1.26 erf approximation, |abs err| <= 1.5e-7
__device__ __forceinline__ float gelu_f(float v){
    float z = fabsf(v)*0.70710678118654752f;
    float t = __fdividef(1.0f, fmaf(0.3275911f, z, 1.0f));
    float p = fmaf(1.061405429f, t, -1.453152027f);
    p = fmaf(p, t, 1.421413741f);
    p = fmaf(p, t, -0.284496736f);
    p = fmaf(p, t, 0.254829592f);
    p *= t;
    float e = __expf(-z*z);
    float er = fmaf(-p, e, 1.0f);
    return v * (0.5f*(1.0f + copysignf(er, v)));
}
__device__ __forceinline__ float f2tf32(float x){
    uint32_t r; asm("cvt.rna.tf32.f32 %0, %1;" : "=r"(r) : "f"(x));
    return __uint_as_float(r);
}
__device__ __forceinline__ void mma_tf32(float& d0,float& d1,float& d2,float& d3,
                                         float a0,float a1,float a2,float a3,
                                         float b0,float b1){
    asm volatile("mma.sync.aligned.m16n8k8.row.col.f32.tf32.tf32.f32 "
        "{%0,%1,%2,%3}, {%4,%5,%6,%7}, {%8,%9}, {%0,%1,%2,%3};"
        : "+f"(d0),"+f"(d1),"+f"(d2),"+f"(d3)
        : "r"(__float_as_uint(a0)),"r"(__float_as_uint(a1)),
          "r"(__float_as_uint(a2)),"r"(__float_as_uint(a3)),
          "r"(__float_as_uint(b0)),"r"(__float_as_uint(b1)));
}

// ---------------- fused y-DFT epilogue (4-warp) ----------------
__device__ __forceinline__ void dft_epi(const float* __restrict__ HS, int b, int xr,
                                        int warp, int lane){
    int g = lane>>2, t4 = lane&3;
    int mt = warp;
    float c[3][4];
#pragma unroll
    for (int nt=0;nt<3;nt++)
#pragma unroll
        for (int r=0;r<4;r++) c[nt][r]=0.f;
    const float2* TB = (const float2*)g_TYBF;
    for (int kk=0; kk<32; kk++){
        float a0 = HS[(mt*16+g  )*PADH + kk*8+t4];
        float a1 = HS[(mt*16+g+8)*PADH + kk*8+t4];
        float a2 = HS[(mt*16+g  )*PADH + kk*8+t4+4];
        float a3 = HS[(mt*16+g+8)*PADH + kk*8+t4+4];
#pragma unroll
        for (int nt=0;nt<3;nt++){
            float2 bf = __ldg(TB + (kk*3+nt)*32 + lane);
            mma_tf32(c[nt][0],c[nt][1],c[nt][2],c[nt][3], a0,a1,a2,a3, bf.x,bf.y);
        }
    }
    float2* Fy2 = (float2*)g_Fy;
    int o = mt*16+g;
#pragma unroll
    for (int nt=0;nt<3;nt++){
        int ky = nt*4+t4;
        size_t base = (((size_t)(b*MM+ky)*CH + o)<<8) + xr;
        Fy2[base]          = make_float2(c[nt][0], c[nt][1]);
        Fy2[base + (8<<8)] = make_float2(c[nt][2], c[nt][3]);
    }
}

// ---------------- fragment pre-pack ----------------
__global__ void k_frw(const float* __restrict__ pw_w, const float* __restrict__ fc1w){
    int t = blockIdx.x*blockDim.x + threadIdx.x;
    if (t < 6144){                                  // TYinv A-frags
        int k = t>>8, y = t&255;
        int ky2 = k>>1;
        int r2 = (ky2*y) & 255;
        double s2,c2; sincospi(2.0*r2/256.0, &s2, &c2);
        float v;
        if ((k&1)==0) v = (ky2==0)? 1.0f : 2.0f*(float)c2;
        else          v = (ky2==0)? 0.0f : -2.0f*(float)s2;
        int kk=k>>3, kin=k&7, t4=kin&3, kh=kin>>2;
        int yt=y>>4, yin=y&15, g=yin&7, half=yin>>3;
        g_TYF[(((kk*16+yt)<<5) + ((g<<2)|t4))*4 + ((kh<<1)|half)] = f2tf32(v);
    } else if (t < 22528){                          // pw B-frags
        int u = t - 6144;
        int layer = u>>12; int v = u&4095;
        int k = v&63, o = v>>6;
        float w = pw_w[(layer*CH+o)*CH + k];
        int kk=k>>3, kin=k&7, t4=kin&3, kh=kin>>2;
        int ot=o>>3, g=o&7;
        g_PWF[layer*4096 + (((kk*8+ot)<<5)+((g<<2)|t4))*2 + kh] = f2tf32(w);
    } else if (t < 30720){                          // fc1 B-frags
        int u = t - 22528;
        int i = u&63, f = u>>6;
        float w = fc1w[f*CH + i];
        int kk=i>>3, kin=i&7, t4=kin&3, kh=kin>>2;
        int ot=f>>3, g=f&7;
        g_FC1F[(((kk*16+ot)<<5)+((g<<2)|t4))*2 + kh] = f2tf32(w);
    } else if (t < 36864){                          // forward-DFT (y) B-frags
        int u = t - 30720;
        int kk = u/192; int r = u%192;
        int nt = r/64;  int r2 = r%64;
        int lane = r2>>1, kh = r2&1;
        int t4 = lane&3, g = lane>>2;
        int y = kk*8 + t4 + 4*kh;
        int n = nt*8 + g;
        int k = n>>1;
        int rr = (k*y) & 255;
        double s,c; sincospi(2.0*rr/256.0, &s, &c);
        float v = (n&1)? (float)(-s) : (float)c;
        g_TYBF[((kk*3+nt)*32 + lane)*2 + kh] = f2tf32(v);
    } else if (t < 61440){                          // fwd x-DFT A-frags
        int u = t - 36864;
        int slot = u&3, lane = (u>>2)&31, mt = (u>>7)%3, kk = u/384;
        int g = lane>>2, t4 = lane&3, half = slot&1, kh = slot>>1;
        int m = mt*16 + g + 8*half;
        int k = kk*8 + t4 + 4*kh;
        int j = m>>1, ri = m&1;
        int x = k>>1, xi = k&1;
        int keff = (j<12)? j : (j-24);
        int rr = ((keff*x)%256 + 256) & 255;
        double s,c; sincospi(2.0*rr/256.0, &s, &c);
        float v = (ri==0) ? ((xi==0)? (float)c : (float)s)
                          : ((xi==0)? (float)(-s) : (float)c);
        g_F1A[u] = f2tf32(v);
    } else if (t < 86016){                          // inv x-DFT B-frags
        int u = t - 61440;
        int kh = u&1, lane = (u>>1)&31, nt = (u>>6)&63, kk = u>>12;
        int g = lane>>2, t4 = lane&3;
        int k = kk*8 + t4 + 4*kh;
        int j = k>>1, ri = k&1;
        int n = nt*8 + g;
        int x = n>>1, xi = n&1;
        int keff = (j<12)? j : (j-24);
        int rr = ((keff*x)%256 + 256) & 255;
        double s,c; sincospi(2.0*rr/256.0, &s, &c);
        float v = (ri==0) ? ((xi==0)? (float)c : (float)s)
                          : ((xi==0)? (float)(-s) : (float)c);
        g_F2B[u] = f2tf32(v * (1.0f/65536.0f));
    }
}

// ---------------- weight transpose via smem (coalesced both sides) ----------------
#define WMIX_SMEM (2*64*145*4)
__global__ void __launch_bounds__(256) k_wmix(const float* __restrict__ w1,
                                              const float* __restrict__ w2){
    extern __shared__ float sm[];
    float* sre = sm;
    float* sim = sm + 64*145;
    int blk = blockIdx.x;
    int which = blk & 1;
    int li = blk >> 1;
    const float2* src = ((const float2*)(which? w2 : w1)) + (size_t)li*9216;
    for (int t=threadIdx.x; t<9216; t+=256){
        float2 v = src[t];
        int o = t/144, jk = t - o*144;
        sre[o*145+jk] = v.x;
        sim[o*145+jk] = v.y;
    }
    __syncthreads();
    int l = li>>6, i = li&63;
    int warp = threadIdx.x>>5, lane = threadIdx.x&31;
    for (int jk=warp; jk<144; jk+=8){
        int jm = jk/12, ky = jk - jm*12;
        int j = jm + (which? 12:0);
        float2* dst = ((float2*)g_WMIX) + ((size_t)((l*12+ky)*24 + j))*4096 + i*64;
        dst[lane]    = make_float2(sre[lane*145+jk],      sim[lane*145+jk]);
        dst[lane+32] = make_float2(sre[(lane+32)*145+jk], sim[(lane+32)*145+jk]);
    }
}

// ---------------- lift (fc0) -> Fy only ----------------
#define LIFT_SMEM ((CH*PADH + 256)*4)
__global__ void __launch_bounds__(256) k_lift_fy(const float* __restrict__ x,
                                                 const float* __restrict__ fw,
                                                 const float* __restrict__ fb){
    extern __shared__ float HS[];   // [64][PADH]
    float* xs = HS + CH*PADH;
    int b = blockIdx.x>>8, xr = blockIdx.x&255;
    int tid = threadIdx.x;
    if (tid < 64)
        ((float4*)xs)[tid] = ((const float4*)(x + (((size_t)b)<<16) + (xr<<8)))[tid];
    __syncthreads();
    float gx = xr*(1.0f/255.0f);
    for (int t=tid; t<CH*64; t+=256){
        int i=t>>6, q=t&63;
        float w0=__ldg(fw+i*3), w1=__ldg(fw+i*3+1), w2=__ldg(fw+i*3+2);
        float base = w1*gx + __ldg(fb+i);
        float4 hv;
        hv.x = f2tf32(w0*xs[q*4  ] + w2*((q*4  )*(1.0f/255.0f)) + base);
        hv.y = f2tf32(w0*xs[q*4+1] + w2*((q*4+1)*(1.0f/255.0f)) + base);
        hv.z = f2tf32(w0*xs[q*4+2] + w2*((q*4+2)*(1.0f/255.0f)) + base);
        hv.w = f2tf32(w0*xs[q*4+3] + w2*((q*4+3)*(1.0f/255.0f)) + base);
        ((float4*)(HS + i*PADH))[q] = hv;
    }
    __syncthreads();
    if (tid < 128) dft_epi(HS, b, xr, tid>>5, tid&31);
}

// ---------------- K-spec: fused (x-DFT -> mode mix -> x-inverse) per (b,ky) ----------------
#define BF1_F2 (64*8*32)
#define G_STRIDE 65
#define G_F (48*G_STRIDE)
#define AF2_F (6*4*32*4)
#define PB1_F (48*128)
#define SPEC_SMEM ((BF1_F2*2 + G_F + AF2_F + PB1_F)*4)

__global__ void __launch_bounds__(512,1)
k_spec(int layer){
    extern __shared__ float sm[];
    float* BF1f = sm;
    float* Gs   = sm + 2*BF1_F2;
    float* AF2  = Gs + G_F;
    float* PB   = AF2 + AF2_F;
    int b = blockIdx.x/12, ky = blockIdx.x%12;
    int tid = threadIdx.x, lane = tid&31, warp = tid>>5;

    const float2* fy = ((const float2*)g_Fy) + (((size_t)(b*MM+ky))<<14);
    for (int t=tid; t<64*256; t+=512){
        int c = t>>8, x = t&255;
        float2 v = fy[t];
        int nt=c>>3, g=c&7;
        int k0=2*x;
        int kk=k0>>3, t4=k0&3, kh=(k0>>2)&1;
        int base = ((kk*8+nt)<<5);
        BF1f[(base + ((g<<2)|t4    ))*2 + kh] = f2tf32(v.x);
        BF1f[(base + ((g<<2)|(t4+1)))*2 + kh] = f2tf32(v.y);
    }
    __syncthreads();

    {   // GEMM1 balanced split-k
        const float4* A4 = (const float4*)g_F1A;
        const float2* B2 = (const float2*)BF1f;
        for (int u=warp; u<48; u+=16){
            int tile = u%24, khalf = u/24;
            int mt = tile%3, nt = tile/3;
            float c0=0.f,c1=0.f,c2=0.f,c3=0.f;
            int kb = khalf*32;
#pragma unroll 8
            for (int kk=kb; kk<kb+32; kk++){
                float4 a = __ldg(A4 + ((kk*3+mt)<<5)+lane);
                float2 bf = B2[((kk*8+nt)<<5)+lane];
                mma_tf32(c0,c1,c2,c3, a.x,a.y,a.z,a.w, bf.x,bf.y);
            }
            float* pb = PB + u*128 + lane*4;
            pb[0]=c0; pb[1]=c1; pb[2]=c2; pb[3]=c3;
        }
    }
    __syncthreads();
    for (int t=tid; t<3072; t+=512){
        int row = t>>6, col = t&63;
        int mt = row>>4, rr = row&15, g = rr&7, hi = rr>>3;
        int nt = col>>3, cc = col&7, t4 = cc>>1, r0 = (hi<<1)|(cc&1);
        int lidx = g*4+t4;
        int tile = nt*3+mt;
        Gs[row*G_STRIDE+col] = PB[tile*128 + lidx*4 + r0]
                             + PB[(tile+24)*128 + lidx*4 + r0];
    }
    __syncthreads();

    {   // mode mix
        const float2* WM = ((const float2*)g_WMIX) + ((size_t)((layer*12+ky)*24))*4096;
#pragma unroll
        for (int r=0; r<3; r++){
            int item = tid + 512*r;
            int j = item>>6, o = item&63;
            const float2* wrow = WM + j*4096 + o;
            const float* Gr = Gs + (2*j)*G_STRIDE;
            const float* Gi = Gs + (2*j+1)*G_STRIDE;
            float ar0=0.f, ai0=0.f, ar1=0.f, ai1=0.f;
#pragma unroll 8
            for (int i=0;i<64;i+=2){
                float2 wv0 = __ldg(wrow + i*64);
                float2 wv1 = __ldg(wrow + (i+1)*64);
                float g0r = Gr[i],   g0i = Gi[i];
                float g1r = Gr[i+1], g1i = Gi[i+1];
                ar0 += g0r*wv0.x - g0i*wv0.y;
                ai0 += g0r*wv0.y + g0i*wv0.x;
                ar1 += g1r*wv1.x - g1i*wv1.y;
                ai1 += g1r*wv1.y + g1i*wv1.x;
            }
            float ar = ar0+ar1, ai = ai0+ai1;
            int mt=o>>4, half=(o>>3)&1, gg=o&7;
            int k0=2*j;
            int kk=k0>>3, t40=k0&3, kh=(k0>>2)&1;
            int base = ((kk*4+mt)<<5);
            AF2[(base + ((gg<<2)|t40    ))*4 + ((kh<<1)|half)] = f2tf32(ar);
            AF2[(base + ((gg<<2)|(t40+1)))*4 + ((kh<<1)|half)] = f2tf32(ai);
        }
    }
    __syncthreads();

    {   // GEMM2 -> E
        int mt = warp&3, ntb = (warp>>2)<<4;
        float4 Areg[6];
#pragma unroll
        for (int kk=0;kk<6;kk++)
            Areg[kk] = ((const float4*)AF2)[((kk*4+mt)<<5)+lane];
        int g=lane>>2, t4=lane&3;
        const float2* B2 = (const float2*)g_F2B;
        float2* E2 = (float2*)g_E;
        for (int ni=0;ni<16;ni++){
            int nt = ntb+ni;
            float c0=0.f,c1=0.f,c2=0.f,c3=0.f;
#pragma unroll
            for (int kk=0;kk<6;kk++){
                float2 bf = __ldg(B2 + ((kk*64+nt)<<5)+lane);
                mma_tf32(c0,c1,c2,c3, Areg[kk].x,Areg[kk].y,Areg[kk].z,Areg[kk].w,
                         bf.x,bf.y);
            }
            int x = nt*4+t4, o = mt*16+g;
            E2[((size_t)(b*HH+x)*CH + o  )*12 + ky] = make_float2(c0,c1);
            E2[((size_t)(b*HH+x)*CH + o+8)*12 + ky] = make_float2(c2,c3);
        }
    }
}

// ---------------- K5: fused layer; h stored in tf32 fragment layout ------------
#define K5_SMEM ((16640 + 1536 + 64 + 256)*4)

__global__ void __launch_bounds__(256,2)
k_layer(const float* __restrict__ xg, const float* __restrict__ fc0w,
        const float* __restrict__ fc0b, const float* __restrict__ pw_b,
        const float* __restrict__ fc1b, const float* __restrict__ fc2w,
        const float* __restrict__ fc2b, float* __restrict__ out, int layer){
    extern __shared__ float sm[];
    float* AF = sm;                  // h A-frags (16384) / HS overlay (16640) / head-AF
    float* HS = sm;
    float* EF = sm + 16640;          // E B-frags (1536) / head partials
    float* bs = EF + 1536;
    float* xs = bs + 64;
    int b = blockIdx.x >> 8, xr = blockIdx.x & 255;
    int tid = threadIdx.x;

    if (layer == 0){
        if (tid < 64)
            ((float4*)xs)[tid] = ((const float4*)(xg + (((size_t)b)<<16) + (xr<<8)))[tid];
        __syncthreads();
        float gx = xr*(1.0f/255.0f);
        for (int t=tid; t<CH*64; t+=256){
            int i=t>>6, q=t&63;
            float w0=__ldg(fc0w+i*3), w1=__ldg(fc0w+i*3+1), w2=__ldg(fc0w+i*3+2);
            float base = w1*gx + __ldg(fc0b+i);
            int kk=i>>3, kin=i&7, t4=kin&3, kh=kin>>2;
#pragma unroll
            for (int d=0; d<4; d++){
                int y = q*4+d;
                float v = w0*xs[y] + w2*(y*(1.0f/255.0f)) + base;
                int yt=y>>4, yin=y&15, g=yin&7, half=yin>>3;
                AF[(((kk*16+yt)<<5)+((g<<2)|t4))*4 + ((kh<<1)|half)] = f2tf32(v);
            }
        }
    } else {
        // h is already in tf32 fragment layout: straight vector copy
        const float4* hg4 = (const float4*)(g_h + ((size_t)blockIdx.x<<14));
        for (int t=tid; t<4096; t+=256)
            ((float4*)AF)[t] = hg4[t];
    }
    {   // E (coalesced) -> B-frags
        const float* Eb = g_E + ((size_t)(b*HH+xr))*CH*24;
        for (int t=tid; t<KXM*CH; t+=256){
            float v = Eb[t];
            int o = t/24, ke = t%24;
            int kk=ke>>3, t4=ke&3, kh=(ke>>2)&1;
            int ot=o>>3, g=o&7;
            EF[(((kk*8+ot)<<5)+((g<<2)|t4))*2 + kh] = f2tf32(v);
        }
    }
    if (tid<CH) bs[tid]=pw_b[layer*CH+tid];
    __syncthreads();

    int lane = tid & 31, warp = tid >> 5;
    int wy = warp >> 1, wo = warp & 1;

    float c[4][4][4];
#pragma unroll
    for (int mi=0;mi<4;mi++)
#pragma unroll
        for (int ni=0;ni<4;ni++)
#pragma unroll
            for (int r=0;r<4;r++) c[mi][ni][r]=0.f;

    const float2* PW2 = ((const float2*)g_PWF) + layer*2048;
    for (int kk=0; kk<8; kk++){
        float2 bf[4];
#pragma unroll
        for (int ni=0;ni<4;ni++)
            bf[ni] = __ldg(PW2 + ((kk*8 + wo*4+ni)<<5)+lane);
#pragma unroll
        for (int mi=0;mi<4;mi++){
            float4 af = ((const float4*)AF)[((kk*16 + wy*4+mi)<<5)+lane];
#pragma unroll
            for (int ni=0;ni<4;ni++)
                mma_tf32(c[mi][ni][0],c[mi][ni][1],c[mi][ni][2],c[mi][ni][3],
                         af.x,af.y,af.z,af.w, bf[ni].x, bf[ni].y);
        }
    }
    const float4* TY4 = (const float4*)g_TYF;
    for (int kk=0; kk<3; kk++){
        float2 bf[4];
#pragma unroll
        for (int ni=0;ni<4;ni++)
            bf[ni] = ((const float2*)EF)[((kk*8 + wo*4+ni)<<5)+lane];
#pragma unroll
        for (int mi=0;mi<4;mi++){
            float4 af = __ldg(TY4 + ((kk*16 + wy*4+mi)<<5)+lane);
#pragma unroll
            for (int ni=0;ni<4;ni++)
                mma_tf32(c[mi][ni][0],c[mi][ni][1],c[mi][ni][2],c[mi][ni][3],
                         af.x,af.y,af.z,af.w, bf[ni].x, bf[ni].y);
        }
    }

    int g = lane>>2, t4 = lane&3;
    int dogelu = (layer < NLAYERS-1);
#pragma unroll
    for (int mi=0;mi<4;mi++){
#pragma unroll
        for (int ni=0;ni<4;ni++){
            int o = (wo*4+ni)*8 + 2*t4;
            float bb0 = bs[o], bb1 = bs[o+1];
            float v0 = c[mi][ni][0] + bb0;
            float v1 = c[mi][ni][1] + bb1;
            float v2 = c[mi][ni][2] + bb0;
            float v3 = c[mi][ni][3] + bb1;
            if (dogelu){ v0=gelu_f(v0); v1=gelu_f(v1); v2=gelu_f(v2); v3=gelu_f(v3); }
            c[mi][ni][0]=v0; c[mi][ni][1]=v1; c[mi][ni][2]=v2; c[mi][ni][3]=v3;
        }
    }

    if (layer < NLAYERS-1){
        __syncthreads();     // retire AF/EF reads before HS overlay
        // tf32-rounded tile into HS (both the y-DFT input and the h image)
#pragma unroll
        for (int mi=0;mi<4;mi++){
            int y = (wy*4+mi)*16 + g;
#pragma unroll
            for (int ni=0;ni<4;ni++){
                int o = (wo*4+ni)*8 + 2*t4;
                HS[ o   *PADH + y  ] = f2tf32(c[mi][ni][0]);
                HS[(o+1)*PADH + y  ] = f2tf32(c[mi][ni][1]);
                HS[ o   *PADH + y+8] = f2tf32(c[mi][ni][2]);
                HS[(o+1)*PADH + y+8] = f2tf32(c[mi][ni][3]);
            }
        }
        __syncthreads();
        if (warp < 4){
            dft_epi(HS, b, xr, warp, lane);
        } else {
            // overlap: emit h in fragment layout (coalesced STG.128)
            float4* hg4 = (float4*)(g_h + ((size_t)blockIdx.x<<14));
            for (int u=tid-128; u<4096; u+=128){
                int row=u>>5, ln=u&31;
                int kk2=row>>4, yt=row&15, g2=ln>>2, t42=ln&3;
                const float* r0 = HS + (kk2*8+t42)*PADH;
                const float* r1 = r0 + 4*PADH;
                int y0 = yt*16+g2;
                hg4[u] = make_float4(r0[y0], r0[y0+8], r1[y0], r1[y0+8]);
            }
        }
        return;
    }

    // ---------------- layer 3: fused head ----------------
    __syncthreads();
#pragma unroll
    for (int mi=0;mi<4;mi++){
#pragma unroll
        for (int ni=0;ni<4;ni++){
#pragma unroll
            for (int r=0;r<4;r++){
                int o = (wo*4+ni)*8 + 2*t4 + (r&1);
                int y = (wy*4+mi)*16 + g + ((r>>1)<<3);
                int kk=o>>3, kin=o&7, t4n=kin&3, khn=kin>>2;
                int yt=y>>4, yin=y&15, gn=yin&7, halfn=yin>>3;
                AF[(((kk*16+yt)<<5)+((gn<<2)|t4n))*4 + ((khn<<1)|halfn)] =
                    f2tf32(c[mi][ni][r]);
            }
        }
    }
    __syncthreads();

    float* part = EF;
    float s0[4] = {0.f,0.f,0.f,0.f}, s1[4] = {0.f,0.f,0.f,0.f};
    const float2* F2 = (const float2*)g_FC1F;
#pragma unroll
    for (int p=0; p<2; p++){
#pragma unroll
        for (int mi=0;mi<4;mi++)
#pragma unroll
            for (int ni=0;ni<4;ni++)
#pragma unroll
                for (int r=0;r<4;r++) c[mi][ni][r]=0.f;
        for (int kk=0; kk<8; kk++){
            float2 bf[4];
#pragma unroll
            for (int ni=0;ni<4;ni++)
                bf[ni] = __ldg(F2 + ((kk*16 + p*8 + wo*4+ni)<<5)+lane);
#pragma unroll
            for (int mi=0;mi<4;mi++){
                float4 af = ((const float4*)AF)[((kk*16 + wy*4+mi)<<5)+lane];
#pragma unroll
                for (int ni=0;ni<4;ni++)
                    mma_tf32(c[mi][ni][0],c[mi][ni][1],c[mi][ni][2],c[mi][ni][3],
                             af.x,af.y,af.z,af.w, bf[ni].x, bf[ni].y);
            }
        }
#pragma unroll
        for (int mi=0;mi<4;mi++){
#pragma unroll
            for (int ni=0;ni<4;ni++){
                int f = (p*8 + wo*4+ni)*8 + 2*t4;
                float ba = __ldg(fc1b+f), bb = __ldg(fc1b+f+1);
                float wa = __ldg(fc2w+f), wb = __ldg(fc2w+f+1);
                s0[mi] += gelu_f(c[mi][ni][0]+ba)*wa + gelu_f(c[mi][ni][1]+bb)*wb;
                s1[mi] += gelu_f(c[mi][ni][2]+ba)*wa + gelu_f(c[mi][ni][3]+bb)*wb;
            }
        }
    }
#pragma unroll
    for (int mi=0;mi<4;mi++){
        float a0 = s0[mi], a1 = s1[mi];
        a0 += __shfl_xor_sync(0xffffffffu, a0, 1);
        a0 += __shfl_xor_sync(0xffffffffu, a0, 2);
        a1 += __shfl_xor_sync(0xffffffffu, a1, 1);
        a1 += __shfl_xor_sync(0xffffffffu, a1, 2);
        if (t4==0){
            int y = (wy*4+mi)*16 + g;
            part[wo*WW + y]   = a0;
            part[wo*WW + y+8] = a1;
        }
    }
    __syncthreads();
    {
        int y = tid;
        float s = part[y] + part[WW+y] + __ldg(fc2b);
        out[(((size_t)b)<<16) + (xr<<8) + y] = s;
    }
}

// ---------------- launch ----------------
extern "C" void kernel_launch(void* const* d_in, const int* in_sizes, int n_in,
                              void* d_out, int out_size){
    (void)in_sizes; (void)n_in; (void)out_size;
    const float* x     = (const float*)d_in[0];
    const float* fc0_w = (const float*)d_in[1];
    const float* fc0_b = (const float*)d_in[2];
    const float* w1    = (const float*)d_in[3];
    const float* w2    = (const float*)d_in[4];
    const float* pw_w  = (const float*)d_in[5];
    const float* pw_b  = (const float*)d_in[6];
    const float* fc1_w = (const float*)d_in[7];
    const float* fc1_b = (const float*)d_in[8];
    const float* fc2_w = (const float*)d_in[9];
    const float* fc2_b = (const float*)d_in[10];
    float* out = (float*)d_out;

    cudaFuncSetAttribute(k_layer,   cudaFuncAttributeMaxDynamicSharedMemorySize, K5_SMEM);
    cudaFuncSetAttribute(k_spec,    cudaFuncAttributeMaxDynamicSharedMemorySize, SPEC_SMEM);
    cudaFuncSetAttribute(k_lift_fy, cudaFuncAttributeMaxDynamicSharedMemorySize, LIFT_SMEM);
    cudaFuncSetAttribute(k_wmix,    cudaFuncAttributeMaxDynamicSharedMemorySize, WMIX_SMEM);

    k_frw<<<336,256>>>(pw_w, fc1_w);
    k_wmix<<<512,256,WMIX_SMEM>>>(w1, w2);
    k_lift_fy<<<BATCH*HH,256,LIFT_SMEM>>>(x, fc0_w, fc0_b);
    for (int l=0; l<NLAYERS; l++){
        k_spec<<<BATCH*MM,512,SPEC_SMEM>>>(l);
        k_layer<<<BATCH*HH,256,K5_SMEM>>>(x, fc0_w, fc0_b, pw_b,
                                          fc1_b, fc2_w, fc2_b, out, l);
    }
}